// round 3
// baseline (speedup 1.0000x reference)
#include <cuda_runtime.h>
#include <cuda_bf16.h>

#define HW   56
#define TS   59          // padded smem row stride
#define KSEL 30
#define NV   14          // pixels per active thread (224 threads * 14 = 3136)
#define TMAX 64          // tie-list capacity

__global__ __launch_bounds__(256, 4)
void topk_spatial_kernel(const float* __restrict__ x,
                         const float* __restrict__ wgt,
                         const float* __restrict__ bias,
                         float* __restrict__ out,
                         int C)
{
    __shared__ float    tile[58 * TS];   // rows 0..57 (borders zero), stride TS
    __shared__ unsigned hist[256];
    __shared__ float    wsm[10];
    __shared__ unsigned sh_dsel, sh_krem;
    __shared__ int      tcnt;
    __shared__ double   tval[TMAX];
    __shared__ int      tidxs[TMAX];

    const int tid = threadIdx.x;
    const int bc  = blockIdx.x;
    const int ch  = bc % C;
    const float* gx = x   + (size_t)bc * (HW * HW);
    float*       go = out + (size_t)bc * (HW * HW);

    if (tid < 9)  wsm[tid] = wgt[ch * 9 + tid];
    if (tid == 9) wsm[9]   = bias[ch];
    if (tid == 10) tcnt = 0;

    // ---- zero borders of the 58x58 logical tile ----
    if (tid < 232) {
        int i = tid;
        if      (i < 58)  tile[i] = 0.f;
        else if (i < 116) tile[57 * TS + (i - 58)] = 0.f;
        else if (i < 174) tile[(i - 116) * TS] = 0.f;
        else              tile[(i - 174) * TS + 57] = 0.f;
    }

    // ---- load interior, vectorized ----
    const float4* gx4 = reinterpret_cast<const float4*>(gx);
    for (int i = tid; i < (HW * HW) / 4; i += 256) {
        float4 v = gx4[i];
        int p  = i * 4;
        int r  = p / HW;
        int cc = p - r * HW;
        float* t = &tile[(r + 1) * TS + cc + 1];
        t[0] = v.x; t[1] = v.y; t[2] = v.z; t[3] = v.w;
    }
    __syncthreads();

    const double w0 = wsm[0], w1 = wsm[1], w2 = wsm[2];
    const double w3 = wsm[3], w4 = wsm[4], w5 = wsm[5];
    const double w6 = wsm[6], w7 = wsm[7], w8 = wsm[8];
    const double bv = wsm[9];

    const bool active = (tid < 224);
    const int  row  = tid >> 2;           // 0..55
    const int  c0   = (tid & 3) * NV;     // 0,14,28,42
    const int  lane = tid & 31;

    // ---- depthwise 3x3 conv in DOUBLE (exact to ~1e-16), key = RN32(score) ----
    unsigned key[NV];
    if (active) {
        const float* t0 = &tile[row * TS + c0];   // r-1 taps
        const float* t1 = t0 + TS;                // r   taps
        const float* t2 = t1 + TS;                // r+1 taps
        float a0 = t0[0], a1 = t0[1];
        float b0 = t1[0], b1 = t1[1];
        float d0 = t2[0], d1 = t2[1];
        #pragma unroll
        for (int j = 0; j < NV; ++j) {
            float a2 = t0[j + 2], b2 = t1[j + 2], d2 = t2[j + 2];
            double s = bv;
            s = fma(w0, (double)a0, s); s = fma(w1, (double)a1, s);
            s = fma(w2, (double)a2, s); s = fma(w3, (double)b0, s);
            s = fma(w4, (double)b1, s); s = fma(w5, (double)b2, s);
            s = fma(w6, (double)d0, s); s = fma(w7, (double)d1, s);
            s = fma(w8, (double)d2, s);
            float sf = (float)s;                  // correctly-rounded fp32 score
            unsigned u = __float_as_uint(sf);
            key[j] = u ^ ((unsigned)(((int)u) >> 31) | 0x80000000u);
            a0 = a1; a1 = a2; b0 = b1; b1 = b2; d0 = d1; d1 = d2;
        }
    } else {
        #pragma unroll
        for (int j = 0; j < NV; ++j) key[j] = 0u;
    }

    // ---- exact top-KSEL threshold via 4x8-bit radix select (MSB first) ----
    unsigned prefix = 0;
    unsigned krem   = KSEL;
    #pragma unroll
    for (int pass = 0; pass < 4; ++pass) {
        const int shift = 24 - 8 * pass;
        hist[tid] = 0;
        __syncthreads();

        if (active) {
            #pragma unroll
            for (int j = 0; j < NV; ++j) {
                unsigned v = key[j];
                bool ok = (((unsigned long long)v) >> (shift + 8)) ==
                          (unsigned long long)prefix;
                unsigned digit = ok ? ((v >> shift) & 255u) : 0xFFFFFFFFu;
                unsigned m = __match_any_sync(0xFFFFFFFFu, digit);
                if (ok && ((__ffs(m) - 1) == lane))
                    atomicAdd(&hist[digit], (unsigned)__popc(m));
            }
        }
        __syncthreads();

        if (tid < 32) {
            unsigned loc[8];
            unsigned run = 0;
            #pragma unroll
            for (int j = 7; j >= 0; --j) { run += hist[lane * 8 + j]; loc[j] = run; }
            unsigned laneTotal = run;
            unsigned incl = laneTotal;
            #pragma unroll
            for (int d = 1; d < 32; d <<= 1) {
                unsigned t = __shfl_down_sync(0xFFFFFFFFu, incl, d);
                if (lane + d < 32) incl += t;
            }
            unsigned hiSum = incl - laneTotal;
            #pragma unroll
            for (int j = 0; j < 8; ++j) {
                unsigned suf  = hiSum + loc[j];                         // count >= bin
                unsigned sufn = (j < 7) ? (hiSum + loc[j + 1]) : hiSum; // count >  bin
                if (suf >= krem && sufn < krem) {
                    sh_dsel = (unsigned)(lane * 8 + j);
                    sh_krem = krem - sufn;
                }
            }
        }
        __syncthreads();
        prefix = (prefix << 8) | sh_dsel;
        krem   = sh_krem;
    }

    const unsigned Tkey = prefix;  // fp32-rounded key of the rank-KSEL score
    const unsigned kfin = krem;    // how many Tkey-equal elements survive

    // ---- tie resolution: among key==Tkey, order by (double score desc, index asc)
    //      (RN is monotone, so top-30 by double == {key > Tkey} ∪ first kfin ties) ----
    if (active) {
        const float* t0 = &tile[row * TS + c0];
        #pragma unroll
        for (int j = 0; j < NV; ++j) {
            if (key[j] == Tkey) {
                double s = bv;
                s = fma(w0, (double)t0[j],          s);
                s = fma(w1, (double)t0[j + 1],      s);
                s = fma(w2, (double)t0[j + 2],      s);
                s = fma(w3, (double)t0[TS + j],     s);
                s = fma(w4, (double)t0[TS + j + 1], s);
                s = fma(w5, (double)t0[TS + j + 2], s);
                s = fma(w6, (double)t0[2*TS + j],     s);
                s = fma(w7, (double)t0[2*TS + j + 1], s);
                s = fma(w8, (double)t0[2*TS + j + 2], s);
                int pos = atomicAdd(&tcnt, 1);
                if (pos < TMAX) { tval[pos] = s; tidxs[pos] = row * HW + c0 + j; }
            }
        }
    }
    __syncthreads();
    const int ntie = (tcnt < TMAX) ? tcnt : TMAX;

    // ---- apply mask into smem, then coalesced store ----
    if (active) {
        float* t1 = &tile[(row + 1) * TS + c0 + 1];    // center x values (owned)
        #pragma unroll
        for (int j = 0; j < NV; ++j) {
            unsigned kj = key[j];
            bool keep = (kj > Tkey);
            if (kj == Tkey) {
                int myidx = row * HW + c0 + j;
                // find my entry + rank among ties: (value desc, index asc)
                double mys = 0.0;
                for (int q = 0; q < ntie; ++q)
                    if (tidxs[q] == myidx) mys = tval[q];
                unsigned rnk = 0;
                for (int q = 0; q < ntie; ++q) {
                    double v = tval[q];
                    if (v > mys || (v == mys && tidxs[q] < myidx)) rnk++;
                }
                keep = (rnk < kfin);
            }
            // note: masking writes race-free (owner-exclusive region)
            if (!keep) t1[j] = 0.0f;
        }
    }
    __syncthreads();

    float4* go4 = reinterpret_cast<float4*>(go);
    for (int i = tid; i < (HW * HW) / 4; i += 256) {
        int p  = i * 4;
        int r  = p / HW;
        int cc = p - r * HW;
        const float* t = &tile[(r + 1) * TS + cc + 1];
        float4 v;
        v.x = t[0]; v.y = t[1]; v.z = t[2]; v.w = t[3];
        go4[i] = v;
    }
}

extern "C" void kernel_launch(void* const* d_in, const int* in_sizes, int n_in,
                              void* d_out, int out_size)
{
    const float* x  = (const float*)d_in[0];
    const float* w  = (const float*)d_in[1];
    const float* b  = (const float*)d_in[2];
    float*       o  = (float*)d_out;
    int C    = in_sizes[2];               // 384
    int n_bc = in_sizes[0] / (HW * HW);   // 12288
    topk_spatial_kernel<<<n_bc, 256>>>(x, w, b, o, C);
}